// round 2
// baseline (speedup 1.0000x reference)
#include <cuda_runtime.h>
#include <math.h>

// ---------------- problem constants ----------------
#define NEXP 8
#define NB   1024
#define NA   32
#define DTOK 128          // D = dz+da = 96+32
#define FF   1024
#define HH   512
#define NRW  4

// ---------------- scratch (__device__ globals; no allocs) ----------------
__device__ float g_w_in_t [NEXP*DTOK*384];    // [e][k(128)][c(384)]
__device__ float g_w_out_t[NEXP*DTOK*DTOK];   // [e][k][c]
__device__ float g_w1_t   [NEXP*DTOK*FF];     // [e][k(128)][c(1024)]
__device__ float g_w2_t   [NEXP*FF*DTOK];     // [e][k(1024)][c(128)]
__device__ float g_h1t    [4096*HH];          // [k(4096)][c(512)]
__device__ float g_ys     [2u*NB*4096];       // per-slot expert outputs (gate-scaled)
__device__ float4 g_assign[NB];               // (e0, g0, e1, g1)
__device__ float g_lse    [NB];
__device__ float g_hid    [NB*HH];

// smem layout of expert kernel (floats)
#define XS_OFF   0
#define QKV_OFF  4096            // 32 x 388 (padded rows)
#define SC_OFF   16512           // scores 128 x 33 / oproj / facc (ld 128)
#define ATT_OFF  20736           // 32 x 128
#define SM_FLOATS 24832
#define SMEM_BYTES (SM_FLOATS*4)

// ---------------- weight repack (transpose) ----------------
__global__ void repack_kernel(const float* __restrict__ w_in,
                              const float* __restrict__ w_out,
                              const float* __restrict__ w1,
                              const float* __restrict__ w2,
                              const float* __restrict__ hw1) {
    const int N_in  = NEXP*384*DTOK;     // 393216
    const int N_out = NEXP*DTOK*DTOK;    // 131072
    const int N_w1  = NEXP*FF*DTOK;      // 1048576
    const int N_w2  = NEXP*DTOK*FF;      // 1048576
    const int N_h1  = HH*4096;           // 2097152
    const int total = N_in + N_out + N_w1 + N_w2 + N_h1;
    for (int i = blockIdx.x*blockDim.x + threadIdx.x; i < total; i += gridDim.x*blockDim.x) {
        if (i < N_in) {
            int e = i / (384*DTOK); int r = i % (384*DTOK);
            int c = r / DTOK, k = r % DTOK;
            g_w_in_t[e*(384*DTOK) + k*384 + c] = w_in[i];
        } else if (i < N_in + N_out) {
            int j = i - N_in;
            int e = j / (DTOK*DTOK); int r = j % (DTOK*DTOK);
            int c = r / DTOK, k = r % DTOK;
            g_w_out_t[e*(DTOK*DTOK) + k*DTOK + c] = w_out[j];
        } else if (i < N_in + N_out + N_w1) {
            int j = i - N_in - N_out;
            int e = j / (FF*DTOK); int r = j % (FF*DTOK);
            int f = r / DTOK, k = r % DTOK;
            g_w1_t[e*(FF*DTOK) + k*FF + f] = w1[j];
        } else if (i < N_in + N_out + N_w1 + N_w2) {
            int j = i - N_in - N_out - N_w1;
            int e = j / (DTOK*FF); int r = j % (DTOK*FF);
            int d = r / FF, k = r % FF;
            g_w2_t[e*(DTOK*FF) + k*DTOK + d] = w2[j];
        } else {
            int j = i - N_in - N_out - N_w1 - N_w2;
            int c = j / 4096, k = j % 4096;
            g_h1t[k*HH + c] = hw1[j];
        }
    }
}

// ---------------- gating: logits, top-2 gates, lse ----------------
__global__ void gating_kernel(const float* __restrict__ z, const float* __restrict__ a,
                              const float* __restrict__ wg, float* __restrict__ gates_out) {
    int b = blockIdx.x;
    int tid = threadIdx.x, w = tid >> 5, lane = tid & 31;
    __shared__ float lg[NEXP];
    float s = 0.f;
    for (int i = lane; i < 4096; i += 32) {
        int n = i >> 7, d = i & 127;
        float xv = (d < 96) ? z[(b*NA + n)*96 + d] : a[(b*NA + n)*32 + d - 96];
        s += xv * wg[i*NEXP + w];
    }
    #pragma unroll
    for (int o = 16; o; o >>= 1) s += __shfl_xor_sync(0xffffffffu, s, o);
    if (lane == 0) lg[w] = s;
    __syncthreads();
    if (tid == 0) {
        int i0 = 0; float v0 = lg[0];
        for (int e = 1; e < NEXP; e++) if (lg[e] > v0) { v0 = lg[e]; i0 = e; }
        int i1 = -1; float v1 = -1e30f;
        for (int e = 0; e < NEXP; e++) if (e != i0 && lg[e] > v1) { v1 = lg[e]; i1 = e; }
        float g0 = 1.f/(1.f + __expf(v1 - v0));
        float g1 = 1.f - g0;
        for (int e = 0; e < NEXP; e++)
            gates_out[b*NEXP + e] = (e == i0) ? g0 : ((e == i1) ? g1 : 0.f);
        g_assign[b] = make_float4((float)i0, g0, (float)i1, g1);
        float se = 0.f;
        for (int e = 0; e < NEXP; e++) se += __expf(lg[e] - v0);
        g_lse[b] = v0 + logf(se);
    }
}

// ---------------- balance loss ----------------
__device__ __forceinline__ float cv2_of8(const float* v) {
    float m = 0.f;
    for (int i = 0; i < 8; i++) m += v[i];
    m *= 0.125f;
    float q = 0.f;
    for (int i = 0; i < 8; i++) { float d = v[i]-m; q += d*d; }
    float var = q / 7.f;
    return var / (m*m + 1e-10f);
}

__global__ void loss_kernel(const float* __restrict__ gates, float* __restrict__ out) {
    __shared__ float imp[NEXP], ldv[NEXP], red[256];
    int tid = threadIdx.x, w = tid >> 5, lane = tid & 31;
    float s = 0.f, c = 0.f;
    for (int b = lane; b < NB; b += 32) {
        float gv = gates[b*NEXP + w];
        s += gv; if (gv > 0.f) c += 1.f;
    }
    #pragma unroll
    for (int o = 16; o; o >>= 1) {
        s += __shfl_xor_sync(0xffffffffu, s, o);
        c += __shfl_xor_sync(0xffffffffu, c, o);
    }
    if (lane == 0) { imp[w] = s; ldv[w] = c; }
    float ls = 0.f;
    for (int b = tid; b < NB; b += 256) ls += g_lse[b];
    red[tid] = ls; __syncthreads();
    for (int o = 128; o; o >>= 1) { if (tid < o) red[tid] += red[tid+o]; __syncthreads(); }
    if (tid == 0)
        out[12288] = cv2_of8(imp) + cv2_of8(ldv) + red[0]*(1.f/1024.f);
}

// ---------------- generic 32x128 GEMM tile, in smem x global transposed weights ----------------
// out[i][c] = (BIAS? bias[c] : (ACC? out[i][c] : 0)) + sum_k in_s[i*128+k]*wT[k*ldwt+c]
template<bool RELU, bool ACC, bool BIAS>
__device__ __forceinline__ void gemm_tile(const float* in_s,
                                          const float* __restrict__ wT, int ldwt,
                                          const float* __restrict__ bias,
                                          float* out_s, int ldo) {
    int tid = threadIdx.x;
    int c0 = (tid & 31) << 2;
    int r0 = (tid >> 5) << 2;
    float acc[4][4];
    if (BIAS) {
        float4 bv = *(const float4*)(bias + c0);
        #pragma unroll
        for (int r = 0; r < 4; r++) { acc[r][0]=bv.x; acc[r][1]=bv.y; acc[r][2]=bv.z; acc[r][3]=bv.w; }
    } else if (ACC) {
        #pragma unroll
        for (int r = 0; r < 4; r++) {
            float4 ov = *(const float4*)(out_s + (r0+r)*ldo + c0);
            acc[r][0]=ov.x; acc[r][1]=ov.y; acc[r][2]=ov.z; acc[r][3]=ov.w;
        }
    } else {
        #pragma unroll
        for (int r = 0; r < 4; r++) { acc[r][0]=0.f; acc[r][1]=0.f; acc[r][2]=0.f; acc[r][3]=0.f; }
    }
    const float* in0 = in_s + r0*128;
    #pragma unroll 2
    for (int k = 0; k < 128; k += 4) {
        float Ar[4][4];
        #pragma unroll
        for (int r = 0; r < 4; r++) *(float4*)Ar[r] = *(const float4*)(in0 + r*128 + k);
        const float* wp = wT + k*ldwt + c0;
        #pragma unroll
        for (int kk = 0; kk < 4; kk++) {
            float4 wv = *(const float4*)(wp + kk*ldwt);
            #pragma unroll
            for (int r = 0; r < 4; r++) {
                float av = Ar[r][kk];
                acc[r][0] += av*wv.x; acc[r][1] += av*wv.y;
                acc[r][2] += av*wv.z; acc[r][3] += av*wv.w;
            }
        }
    }
    #pragma unroll
    for (int r = 0; r < 4; r++) {
        float4 ov;
        ov.x = RELU ? fmaxf(acc[r][0],0.f) : acc[r][0];
        ov.y = RELU ? fmaxf(acc[r][1],0.f) : acc[r][1];
        ov.z = RELU ? fmaxf(acc[r][2],0.f) : acc[r][2];
        ov.w = RELU ? fmaxf(acc[r][3],0.f) : acc[r][3];
        *(float4*)(out_s + (r0+r)*ldo + c0) = ov;
    }
}

// LayerNorm over 32 rows of 128: warp w handles rows 4w..4w+3 with shuffle reductions.
// dst[row*128+c] = scale * ((xs+add - mu)*rsqrt(var+eps)*g[c] + b[c])
__device__ __forceinline__ void ln_rows(const float* xs, const float* add,
                                        const float* __restrict__ g, const float* __restrict__ bt,
                                        float* dst, float scale) {
    int tid = threadIdx.x, w = tid >> 5, lane = tid & 31;
    float4 gv = *(const float4*)(g + lane*4);
    float4 bv = *(const float4*)(bt + lane*4);
    #pragma unroll
    for (int r = 0; r < 4; r++) {
        int row = w*4 + r;
        float4 xv = *(const float4*)(xs + row*128 + lane*4);
        float4 ov = *(const float4*)(add + row*128 + lane*4);
        float vx = xv.x+ov.x, vy = xv.y+ov.y, vz = xv.z+ov.z, vw = xv.w+ov.w;
        float s = vx+vy+vz+vw;
        #pragma unroll
        for (int o = 16; o; o >>= 1) s += __shfl_xor_sync(0xffffffffu, s, o);
        float mu = s*(1.f/128.f);
        float dx = vx-mu, dy = vy-mu, dz = vz-mu, dw = vw-mu;
        float q = dx*dx+dy*dy+dz*dz+dw*dw;
        #pragma unroll
        for (int o = 16; o; o >>= 1) q += __shfl_xor_sync(0xffffffffu, q, o);
        float rs = rsqrtf(q*(1.f/128.f) + 1e-5f);
        float4 res;
        res.x = (dx*rs*gv.x + bv.x)*scale;
        res.y = (dy*rs*gv.y + bv.y)*scale;
        res.z = (dz*rs*gv.z + bv.z)*scale;
        res.w = (dw*rs*gv.w + bv.w)*scale;
        *(float4*)(dst + row*128 + lane*4) = res;
    }
}

// ---------------- expert kernel: one block per (batch, slot) ----------------
__global__ void __launch_bounds__(256, 2)
expert_kernel(const float* __restrict__ z, const float* __restrict__ a,
              const float* __restrict__ b_in, const float* __restrict__ b_out,
              const float* __restrict__ ln1g, const float* __restrict__ ln1b,
              const float* __restrict__ b1, const float* __restrict__ b2,
              const float* __restrict__ ln2g, const float* __restrict__ ln2b) {
    extern __shared__ float sm[];
    float* xs  = sm + XS_OFF;    // 32x128  (x, later h)
    float* qkv = sm + QKV_OFF;   // 32x388 padded
    float* sc  = sm + SC_OFF;    // scores 128x33 / oproj / facc
    float* att = sm + ATT_OFF;   // 32x128 (attn out, later act chunk)
    int tid = threadIdx.x;
    int bs = blockIdx.x, b = bs >> 1, slot = bs & 1;
    float4 as = g_assign[b];
    int e; float gate;
    if (slot == 0) { e = (int)as.x; gate = as.y; } else { e = (int)as.z; gate = as.w; }

    // load x = concat(z, a)
    for (int i = tid; i < 4096; i += 256) {
        int n = i >> 7, d = i & 127;
        xs[i] = (d < 96) ? z[(b*NA + n)*96 + d] : a[(b*NA + n)*32 + d - 96];
    }
    __syncthreads();

    // qkv = x @ w_in.T + b_in  -> [32, 384]
    {
        const float* wit = g_w_in_t + e*(128*384);
        const float* bi  = b_in + e*384;
        #pragma unroll 1
        for (int p = 0; p < 3; p++)
            gemm_tile<false,false,true>(xs, wit + p*128, 384, bi + p*128, qkv + p*128, 388);
    }
    __syncthreads();

    // attention scores -> sc[(h*32+i)*33 + j]
    for (int t = tid; t < 4096; t += 256) {
        int j = t & 31, hi = t >> 5;
        int h = hi >> 5, i = hi & 31;
        const float* qq = qkv + i*388 + h*32;
        const float* kk = qkv + j*388 + 128 + h*32;
        float s = 0.f;
        #pragma unroll
        for (int d = 0; d < 32; d++) s += qq[d]*kk[d];
        sc[hi*33 + j] = s * 0.17677669529663687f;   // 1/sqrt(32)
    }
    __syncthreads();
    // softmax over j
    if (tid < 128) {
        float* row = sc + tid*33;
        float m = row[0];
        #pragma unroll
        for (int j = 1; j < 32; j++) m = fmaxf(m, row[j]);
        float ssum = 0.f;
        #pragma unroll
        for (int j = 0; j < 32; j++) { float ev = __expf(row[j]-m); row[j] = ev; ssum += ev; }
        float inv = 1.f/ssum;
        #pragma unroll
        for (int j = 0; j < 32; j++) row[j] *= inv;
    }
    __syncthreads();
    // attn output -> att[32,128]
    for (int t = tid; t < 4096; t += 256) {
        int i = t >> 7, c = t & 127, h = c >> 5;
        const float* pr = sc + (h*32 + i)*33;
        const float* vv = qkv + 256 + c;
        float s = 0.f;
        #pragma unroll
        for (int j = 0; j < 32; j++) s += pr[j]*vv[j*388];
        att[t] = s;
    }
    __syncthreads();
    // o-proj -> sc (ld 128)
    gemm_tile<false,false,true>(att, g_w_out_t + e*(128*128), 128, b_out + e*128, sc, 128);
    __syncthreads();
    // h = LN(x + o) -> xs
    ln_rows(xs, sc, ln1g + e*128, ln1b + e*128, xs, 1.f);
    __syncthreads();

    // FFN: facc in sc, act chunk in att
    const float* w1t = g_w1_t + e*(128*1024);
    const float* w2t = g_w2_t + e*(1024*128);
    const float* b1e = b1 + e*1024;
    #pragma unroll 1
    for (int ch = 0; ch < 8; ch++) {
        gemm_tile<true,false,true>(xs, w1t + ch*128, 1024, b1e + ch*128, att, 128);
        __syncthreads();
        if (ch == 0) gemm_tile<false,false,true>(att, w2t + ch*128*128, 128, b2 + e*128, sc, 128);
        else         gemm_tile<false,true ,false>(att, w2t + ch*128*128, 128, (const float*)0, sc, 128);
        __syncthreads();
    }

    // out = gate * LN(h + f) -> g_ys[slot][b]
    ln_rows(xs, sc, ln2g + e*128, ln2b + e*128,
            g_ys + ((size_t)slot*NB + b)*4096, gate);
}

// ---------------- head 1: hid = relu((ys0+ys1) @ head_w1.T + b1) ----------------
__global__ void __launch_bounds__(256)
head1_kernel(const float* __restrict__ hb1) {
    __shared__ float xt[32*128];
    int tid = threadIdx.x;
    int rowbase = blockIdx.x * 32;
    int colbase = blockIdx.y * 128;
    int c0 = (tid & 31) << 2;
    int r0 = (tid >> 5) << 2;
    float acc[4][4];
    {
        float4 bv = *(const float4*)(hb1 + colbase + c0);
        #pragma unroll
        for (int r = 0; r < 4; r++) { acc[r][0]=bv.x; acc[r][1]=bv.y; acc[r][2]=bv.z; acc[r][3]=bv.w; }
    }
    for (int kc = 0; kc < 4096; kc += 128) {
        __syncthreads();
        for (int i = tid; i < 4096; i += 256) {
            int rr = i >> 7, cc = i & 127;
            size_t gi = (size_t)(rowbase + rr)*4096 + kc + cc;
            xt[i] = g_ys[gi] + g_ys[(size_t)NB*4096 + gi];
        }
        __syncthreads();
        const float* wp0 = g_h1t + (size_t)kc*HH + colbase + c0;
        const float* in0 = xt + r0*128;
        #pragma unroll 2
        for (int k = 0; k < 128; k += 4) {
            float Ar[4][4];
            #pragma unroll
            for (int r = 0; r < 4; r++) *(float4*)Ar[r] = *(const float4*)(in0 + r*128 + k);
            #pragma unroll
            for (int kk = 0; kk < 4; kk++) {
                float4 wv = *(const float4*)(wp0 + (k+kk)*HH);
                #pragma unroll
                for (int r = 0; r < 4; r++) {
                    float av = Ar[r][kk];
                    acc[r][0] += av*wv.x; acc[r][1] += av*wv.y;
                    acc[r][2] += av*wv.z; acc[r][3] += av*wv.w;
                }
            }
        }
    }
    #pragma unroll
    for (int r = 0; r < 4; r++) {
        float4 ov;
        ov.x = fmaxf(acc[r][0],0.f); ov.y = fmaxf(acc[r][1],0.f);
        ov.z = fmaxf(acc[r][2],0.f); ov.w = fmaxf(acc[r][3],0.f);
        *(float4*)(g_hid + (size_t)(rowbase + r0 + r)*HH + colbase + c0) = ov;
    }
}

// ---------------- head 2: r = hid @ head_w2.T + b2 ----------------
__global__ void head2_kernel(const float* __restrict__ w2h, const float* __restrict__ b2h,
                             float* __restrict__ out) {
    int b = blockIdx.x;
    int w = threadIdx.x >> 5, lane = threadIdx.x & 31;
    const float* hp = g_hid + (size_t)b*HH;
    const float* wp = w2h + w*HH;
    float s = 0.f;
    for (int i = lane; i < HH; i += 32) s += hp[i]*wp[i];
    #pragma unroll
    for (int o = 16; o; o >>= 1) s += __shfl_xor_sync(0xffffffffu, s, o);
    if (lane == 0) out[b*NRW + w] = s + b2h[w];
}

// ---------------- launch ----------------
extern "C" void kernel_launch(void* const* d_in, const int* in_sizes, int n_in,
                              void* d_out, int out_size) {
    const float* z     = (const float*)d_in[0];
    const float* a     = (const float*)d_in[1];
    const float* w_gate= (const float*)d_in[2];
    const float* w_in  = (const float*)d_in[3];
    const float* b_in  = (const float*)d_in[4];
    const float* w_out = (const float*)d_in[5];
    const float* b_out = (const float*)d_in[6];
    const float* ln1g  = (const float*)d_in[7];
    const float* ln1b  = (const float*)d_in[8];
    const float* w1    = (const float*)d_in[9];
    const float* b1    = (const float*)d_in[10];
    const float* w2    = (const float*)d_in[11];
    const float* b2    = (const float*)d_in[12];
    const float* ln2g  = (const float*)d_in[13];
    const float* ln2b  = (const float*)d_in[14];
    const float* hw1   = (const float*)d_in[15];
    const float* hb1   = (const float*)d_in[16];
    const float* hw2   = (const float*)d_in[17];
    const float* hb2   = (const float*)d_in[18];
    float* out = (float*)d_out;

    cudaFuncSetAttribute((const void*)expert_kernel,
                         cudaFuncAttributeMaxDynamicSharedMemorySize, SMEM_BYTES);

    repack_kernel<<<4096, 256>>>(w_in, w_out, w1, w2, hw1);
    gating_kernel<<<NB, 256>>>(z, a, w_gate, out + 4096);
    loss_kernel<<<1, 256>>>(out + 4096, out);
    expert_kernel<<<2*NB, 256, SMEM_BYTES>>>(z, a, b_in, b_out, ln1g, ln1b,
                                             b1, b2, ln2g, ln2b);
    head1_kernel<<<dim3(32, 4), 256>>>(hb1);
    head2_kernel<<<NB, 128>>>(hw2, hb2, out);
}